// round 14
// baseline (speedup 1.0000x reference)
#include <cuda_runtime.h>
#include <math.h>

#define Bn 8
#define Cc 64
#define Hh 256
#define Ww 256
#define Ll 4
#define M1 20
#define M2 20
#define BC (Bn*Cc)          // 512
#define HW (Hh*Ww)          // 65536
#define NPIX (Bn*HW)        // 524288
#define NTOT (BC*HW)        // 33554432

// packed f32x2 ops (sm_100+; only reachable via PTX — ptxas never auto-fuses)
#define FMA2(acc, a, b) \
    asm("fma.rn.f32x2 %0, %1, %2, %0;" : "+l"(acc) : "l"(a), "l"(b))
#define ADDF2(a, b) \
    asm("add.rn.f32x2 %0, %0, %1;" : "+l"(a) : "l"(b))
#define PACKF2(out, v) \
    asm("mov.b64 %0, {%1, %1};" : "=l"(out) : "r"(__float_as_uint(v)))

// cp.async (LDGSTS) helpers — no register staging, background copy
__device__ __forceinline__ void cp_async4(unsigned dst, const float* src, bool pred) {
    int sz = pred ? 4 : 0;                         // src-size 0 => zero-fill
    asm volatile("cp.async.ca.shared.global [%0], [%1], 4, %2;"
                 :: "r"(dst), "l"(src), "r"(sz));
}
__device__ __forceinline__ void cp_async16(unsigned dst, const float4* src) {
    asm volatile("cp.async.ca.shared.global [%0], [%1], 16;" :: "r"(dst), "l"(src));
}
#define CP_COMMIT() asm volatile("cp.async.commit_group;")
#define CP_WAIT0()  asm volatile("cp.async.wait_group 0;")

// ---------------- scratch (device globals; no allocations allowed) ----------
__device__ float g_h0[NTOT];                 // ping
__device__ float g_h1[NTOT];                 // pong
__device__ float g_F [BC*2*M1*M2*2];         // fwd result (bc,kyi,kx) complex
__device__ float g_D [BC*2*M1*M2*2];         // after channel mix
__device__ float g_wt[Ll*Cc*9*Cc];           // combined conv weights [l][ci][tap][co]
__device__ float g_bc2[Ll*Cc];               // combined conv bias
__device__ float g_wm[Ll*40*20*Cc*Cc*2];     // mode-contiguous mix weights [l][kyi][kx][i][o][2]
__device__ float g_cx[M2*Hh];                // cos(2pi k x/256), [k][x]
__device__ float g_sx[M2*Hh];                // sin(2pi k x/256), [k][x]
__device__ float g_cx2[10*Hh*2];             // paired cos: [kp][x][{2kp, 2kp+1}]
__device__ float g_sx2[10*Hh*2];             // paired sin
__device__ float g_cy[Hh*2*M1];              // [y][kyi], ky = kyi<20?kyi:216+kyi
__device__ float g_sy[Hh*2*M1];

// ---------------- prep: fold convh+convw+pw into one 3x3 conv ---------------
__global__ void k_prep_w(const float* __restrict__ ch, const float* __restrict__ cw,
                         const float* __restrict__ pw, const float* __restrict__ bh,
                         const float* __restrict__ bw, const float* __restrict__ bp)
{
    int idx = blockIdx.x*blockDim.x + threadIdx.x;
    int total = Ll*Cc*Cc*9;
    if (idx < total) {
        // destination layout: [l][ci][tap][co]  (co fastest -> co-pairs are contiguous)
        int co  = idx & 63;
        int tap = (idx >> 6) % 9;
        int ci  = (idx / (64*9)) & 63;
        int l   = idx / (64*9*64);
        int src = ((l*64 + co)*64 + ci)*9 + tap;       // source: (L,O,I,3,3)
        float v = ch[src] + cw[src];
        if (tap == 4) v += pw[(l*64 + co)*64 + ci];    // 1x1 folded into center
        g_wt[idx] = v;
    }
    if (idx < Ll*Cc) g_bc2[idx] = bh[idx] + bw[idx] + bp[idx];
}

// repack spectral weights, both directions coalesced via smem staging.
// block = (arr, l, i); loops 8 o-chunks; src rows contiguous, dst 64B chunks.
__global__ __launch_bounds__(256) void k_prep_wmix(const float* __restrict__ w1,
                                                   const float* __restrict__ w2)
{
    int bid = blockIdx.x;                              // 512 blocks
    int i   = bid & 63;
    int l   = (bid >> 6) & 3;
    int arr = bid >> 8;
    const float* w = arr ? w2 : w1;
    __shared__ float sm[8*800];
    int t = threadIdx.x;

    for (int oc = 0; oc < 8; oc++) {
        __syncthreads();
        const float* src = w + ((size_t)(l*64 + i)*64 + oc*8)*800;  // 8 o-rows x 800 floats
        for (int e = t; e < 8*800; e += 256) sm[e] = src[e];
        __syncthreads();
        for (int e = t; e < 400*16; e += 256) {
            int m = e >> 4, f = e & 15;                // m = kk*20+kx
            int o = oc*8 + (f >> 1), ri = f & 1;
            int kk = m / 20, kx = m % 20;
            int kyi = arr ? (20 + kk) : kk;
            g_wm[((((size_t)(l*40 + kyi)*20 + kx)*64 + i)*64 + o)*2 + ri] =
                sm[(o - oc*8)*800 + m*2 + ri];
        }
    }
}

__global__ void k_prep_trig()
{
    int idx = blockIdx.x*blockDim.x + threadIdx.x;
    if (idx < M2*Hh) {                                  // [k][x]
        int k = idx >> 8, x = idx & 255;
        int m = (k*x) & 255;                            // exact angle reduction
        double t = (double)m * (6.283185307179586476925287 / 256.0);
        double s, c; sincos(t, &s, &c);
        g_cx[idx] = (float)c; g_sx[idx] = (float)s;
    }
    if (idx < 10*Hh) {                                  // paired [kp][x] (k=2kp, 2kp+1)
        int kp = idx >> 8, x = idx & 255;
        int m0 = ((2*kp)*x) & 255;
        int m1 = ((2*kp+1)*x) & 255;
        double t0 = (double)m0 * (6.283185307179586476925287 / 256.0);
        double t1 = (double)m1 * (6.283185307179586476925287 / 256.0);
        double s0, c0, s1, c1; sincos(t0, &s0, &c0); sincos(t1, &s1, &c1);
        g_cx2[idx*2]   = (float)c0; g_cx2[idx*2+1] = (float)c1;
        g_sx2[idx*2]   = (float)s0; g_sx2[idx*2+1] = (float)s1;
    }
    if (idx < Hh*2*M1) {                                // [y][kyi]
        int y = idx / 40, kyi = idx % 40;
        int ky = (kyi < 20) ? kyi : (216 + kyi);        // 236..255
        int m = (ky*y) & 255;
        double t = (double)m * (6.283185307179586476925287 / 256.0);
        double s, c; sincos(t, &s, &c);
        g_cy[idx] = (float)c; g_sy[idx] = (float)s;
    }
}

// ---------------- fc0 lift: thread = 4 px x all 64 c ------------------------
__global__ __launch_bounds__(256) void k_fc0(const float* __restrict__ xin,
                                             const float* __restrict__ w,
                                             const float* __restrict__ b)
{
    int i4 = blockIdx.x*256 + threadIdx.x;              // over NPIX/4 = 131072
    if (i4 >= NPIX/4) return;
    int x4 = (i4 & 63) * 4;
    int y  = (i4 >> 6) & 255;
    int bb = i4 >> 14;
    const float* xp = xin + ((size_t)(bb*Hh + y)*Ww + x4)*3;
    float4 p0 = *(const float4*)(xp);                   // 12 consecutive floats
    float4 p1 = *(const float4*)(xp + 4);
    float4 p2 = *(const float4*)(xp + 8);
    float v0x = p0.x, v0y = p0.y, v0z = p0.z;           // px0
    float v1x = p0.w, v1y = p1.x, v1z = p1.y;           // px1
    float v2x = p1.z, v2y = p1.w, v2z = p2.x;           // px2
    float v3x = p2.y, v3y = p2.z, v3z = p2.w;           // px3
    float* dst = g_h0 + (size_t)bb*Cc*HW + (size_t)y*256 + x4;
#pragma unroll 4
    for (int c = 0; c < 64; c++) {
        float w0 = __ldg(&w[c]), w1 = __ldg(&w[64+c]), w2 = __ldg(&w[128+c]);
        float bs = __ldg(&b[c]);
        float4 r;
        r.x = bs + v0x*w0 + v0y*w1 + v0z*w2;
        r.y = bs + v1x*w0 + v1y*w1 + v1z*w2;
        r.z = bs + v2x*w0 + v2y*w1 + v2z*w2;
        r.w = bs + v3x*w0 + v3y*w1 + v3z*w2;
        *(float4*)&dst[(size_t)c*HW] = r;
    }
}

// ---------------- combined 3x3 conv (NCHW), f32x2 + cp.async pipeline -------
__global__ __launch_bounds__(256, 2) void k_conv(int l, int sel)
{
    const float* hin = sel ? g_h1 : g_h0;
    float*      hout = sel ? g_h0 : g_h1;

    __shared__ float s_in[2][8][10][36];              // 2 x 11.25KB
    __shared__ __align__(16) float s_w[2][8*9*64];    // 2 x 18KB

    int t  = threadIdx.x;
    int cog = t & 7;                                  // co group: 8 co each
    int p   = t >> 3;                                 // 0..31 pixel group
    int px8 = (p & 3) * 8;                            // x offset within tile
    int py  = p >> 2;                                 // 0..7
    int x0 = blockIdx.x * 32;
    int y0 = blockIdx.y * 8;
    int b  = blockIdx.z;
    const float* hb = hin + (size_t)b*Cc*HW;

    auto issue = [&](int cc, int buf) {
        unsigned sin_b = (unsigned)__cvta_generic_to_shared(&s_in[buf][0][0][0]);
        unsigned sw_b  = (unsigned)__cvta_generic_to_shared(&s_w[buf][0]);
        for (int e = t; e < 8*10*34; e += 256) {
            int ci = e / 340;
            int r  = e % 340;
            int dy = r / 34, dx = r % 34;
            int gy = y0 + dy - 1, gx = x0 + dx - 1;
            bool ok = (gy >= 0 && gy < 256 && gx >= 0 && gx < 256);
            const float* src = ok ? &hb[(size_t)(cc*8 + ci)*HW + gy*256 + gx] : hb;
            cp_async4(sin_b + (unsigned)(((ci*10 + dy)*36 + dx)*4), src, ok);
        }
        const float4* wsrc = (const float4*)&g_wt[((l*64 + cc*8)*9)*64];
        for (int e = t; e < 8*9*16; e += 256)
            cp_async16(sw_b + (unsigned)(e*16), wsrc + e);
        CP_COMMIT();
    };

    unsigned long long accp[4][8];
#pragma unroll
    for (int i = 0; i < 4; i++)
#pragma unroll
        for (int q = 0; q < 8; q++) accp[i][q] = 0ULL;   // (0.f,0.f)

    issue(0, 0);
    for (int cc = 0; cc < 8; cc++) {
        int buf = cc & 1;
        CP_WAIT0();
        __syncthreads();
        if (cc < 7) issue(cc + 1, buf ^ 1);

#pragma unroll
        for (int ci = 0; ci < 8; ci++) {
#pragma unroll
            for (int fy = 0; fy < 3; fy++) {
                const float* rp = &s_in[buf][ci][py+fy][px8];
                float4 a4 = *(const float4*)rp;
                float4 b4 = *(const float4*)(rp + 4);
                float2 c2 = *(const float2*)(rp + 8);
                unsigned long long xs[10];
                PACKF2(xs[0], a4.x); PACKF2(xs[1], a4.y);
                PACKF2(xs[2], a4.z); PACKF2(xs[3], a4.w);
                PACKF2(xs[4], b4.x); PACKF2(xs[5], b4.y);
                PACKF2(xs[6], b4.z); PACKF2(xs[7], b4.w);
                PACKF2(xs[8], c2.x); PACKF2(xs[9], c2.y);
#pragma unroll
                for (int fx = 0; fx < 3; fx++) {
                    const ulonglong2* wp =
                        (const ulonglong2*)&s_w[buf][(ci*9 + fy*3 + fx)*64 + cog*8];
                    ulonglong2 w0 = wp[0];
                    ulonglong2 w1 = wp[1];
#pragma unroll
                    for (int q = 0; q < 8; q++) {
                        FMA2(accp[0][q], w0.x, xs[fx+q]);
                        FMA2(accp[1][q], w0.y, xs[fx+q]);
                        FMA2(accp[2][q], w1.x, xs[fx+q]);
                        FMA2(accp[3][q], w1.y, xs[fx+q]);
                    }
                }
            }
        }
    }

    float* ob = hout + (size_t)b*Cc*HW + (size_t)(y0+py)*256 + (x0+px8);
#pragma unroll
    for (int pr = 0; pr < 4; pr++) {
        int co0 = cog*8 + 2*pr;
        float b0 = __ldg(&g_bc2[l*64 + co0]);
        float b1 = __ldg(&g_bc2[l*64 + co0 + 1]);
        float2 q0 = *(float2*)&accp[pr][0];
        float2 q1 = *(float2*)&accp[pr][1];
        float2 q2 = *(float2*)&accp[pr][2];
        float2 q3 = *(float2*)&accp[pr][3];
        float2 q4 = *(float2*)&accp[pr][4];
        float2 q5 = *(float2*)&accp[pr][5];
        float2 q6 = *(float2*)&accp[pr][6];
        float2 q7 = *(float2*)&accp[pr][7];
        float* r0 = &ob[(size_t)co0*HW];
        float* r1 = &ob[(size_t)(co0+1)*HW];
        *(float4*)(r0    ) = make_float4(q0.x+b0, q1.x+b0, q2.x+b0, q3.x+b0);
        *(float4*)(r0 + 4) = make_float4(q4.x+b0, q5.x+b0, q6.x+b0, q7.x+b0);
        *(float4*)(r1    ) = make_float4(q0.y+b1, q1.y+b1, q2.y+b1, q3.y+b1);
        *(float4*)(r1 + 4) = make_float4(q4.y+b1, q5.y+b1, q6.y+b1, q7.y+b1);
    }
}

// ---------------- fused forward DFT (x then y), block per bc ----------------
// Phase 1: 32 warps x 8 rows, k-paired f32x2 shuffle DFT -> sX in smem.
// Phase 2: (kx, kyi) threads reduce over y -> g_F. No g_xf round-trip.
__global__ __launch_bounds__(1024) void k_fwd(int sel)
{
    const float* hin = sel ? g_h1 : g_h0;
    __shared__ __align__(8) float sc2[10*Hh*2];       // 20KB
    __shared__ __align__(8) float ss2[10*Hh*2];       // 20KB
    __shared__ float sX[Hh*M2*2];                     // 40KB
    int t = threadIdx.x;
    int bc = blockIdx.x;
    for (int e = t; e < 10*Hh*2; e += 1024) { sc2[e] = g_cx2[e]; ss2[e] = g_sx2[e]; }
    __syncthreads();

    // ---- phase 1: x-DFT (identical arithmetic to previous k_fwdx) ----
    {
        int warp = t >> 5, lane = t & 31;
        for (int rr = 0; rr < 8; rr++) {
            int y = warp*8 + rr;
            const float* rp = hin + ((size_t)bc*256 + y) * 256;
            unsigned long long vs[8];
#pragma unroll
            for (int j = 0; j < 8; j++) { float v = rp[lane + 32*j]; PACKF2(vs[j], v); }

            float* outp = &sX[y*40];
            for (int kp = 0; kp < 10; kp++) {
                unsigned long long ar = 0ULL, ai = 0ULL;
#pragma unroll
                for (int j = 0; j < 8; j++) {
                    int x = lane + 32*j;
                    unsigned long long c2 = *(const unsigned long long*)&sc2[(kp*256 + x)*2];
                    unsigned long long s2 = *(const unsigned long long*)&ss2[(kp*256 + x)*2];
                    FMA2(ar, vs[j], c2);
                    FMA2(ai, vs[j], s2);
                }
#pragma unroll
                for (int o = 16; o > 0; o >>= 1) {
                    unsigned long long t1 = __shfl_xor_sync(0xffffffffu, ar, o);
                    unsigned long long t2 = __shfl_xor_sync(0xffffffffu, ai, o);
                    ADDF2(ar, t1);
                    ADDF2(ai, t2);
                }
                if (lane == 0) {
                    float2 arf = *(float2*)&ar;
                    float2 aif = *(float2*)&ai;
                    outp[4*kp+0] =  arf.x*0.0625f;
                    outp[4*kp+1] = -(aif.x*0.0625f);
                    outp[4*kp+2] =  arf.y*0.0625f;
                    outp[4*kp+3] = -(aif.y*0.0625f);
                }
            }
        }
    }
    __syncthreads();

    // ---- phase 2: y-DFT (identical arithmetic to previous k_fwdy) ----
    if (t < 800) {
        int kx = t % 20, kyi = t / 20;                // kyi in [0,40)
        float ar = 0.f, ai = 0.f;
#pragma unroll 4
        for (int y = 0; y < 256; y++) {
            float xr = sX[(y*20 + kx)*2], xi = sX[(y*20 + kx)*2 + 1];
            float c = __ldg(&g_cy[y*40 + kyi]), s = __ldg(&g_sy[y*40 + kyi]);
            ar += xr*c + xi*s;                        // X * e^{-i th}
            ai += xi*c - xr*s;
        }
        size_t o = ((size_t)(bc*40 + kyi)*20 + kx)*2;
        g_F[o]   = ar*0.0625f;
        g_F[o+1] = ai*0.0625f;
    }
}

// ---------------- per-mode 64x64 complex channel mix ------------------------
__global__ __launch_bounds__(512) void k_mix(int l)
{
    __shared__ __align__(16) float sW[Cc*Cc*2];       // [i][o] complex, 32KB
    __shared__ float sF[Bn*Cc*2];                     // [b][i] complex, 4KB
    int m   = blockIdx.x;                             // 0..799
    int kyi = m / 20, kx = m % 20;
    int t = threadIdx.x;

    {
        const float4* src4 = (const float4*)&g_wm[(size_t)(l*800 + m) * (Cc*Cc*2)];
        float4* dst4 = (float4*)sW;
        for (int e = t; e < Cc*Cc*2/4; e += 512) dst4[e] = src4[e];
    }
    {
        int e = t;                                    // e = b*64+i  (512 threads)
        size_t s = (((size_t)e*40 + kyi)*20 + kx)*2;
        sF[e*2]   = g_F[s];
        sF[e*2+1] = g_F[s+1];
    }
    __syncthreads();

    int o = t & 63, b = t >> 6;
    float ar = 0.f, ai = 0.f;
#pragma unroll 4
    for (int i = 0; i < 64; i++) {
        float fr = sF[(b*64 + i)*2], fi = sF[(b*64 + i)*2 + 1];
        float wr = sW[(i*64 + o)*2], wi = sW[(i*64 + o)*2 + 1];
        ar += fr*wr - fi*wi;
        ai += fr*wi + fi*wr;
    }
    size_t d = (((size_t)(b*64 + o)*40 + kyi)*20 + kx)*2;
    g_D[d] = ar; g_D[d+1] = ai;
}

// ---------------- fused inverse DFT (y then x) + add conv + GeLU ------------
// Block per bc. Phase 1: inv-y into sg (smem, no g_gy round-trip).
// Phase 2: x-paired inv-x, RMW on conv output, optional GeLU.
__global__ __launch_bounds__(1024) void k_inv(int sel, int do_gelu)
{
    float* hout = sel ? g_h0 : g_h1;                  // conv output buffer
    __shared__ float sD[2*M1*M2*2];                   // 6.4KB
    __shared__ float sg[Hh][40];                      // 40KB
    __shared__ __align__(8) float sc[M2*Hh];          // 20KB
    __shared__ __align__(8) float ss[M2*Hh];          // 20KB
    int t = threadIdx.x;
    int bc = blockIdx.x;

    const float* src = g_D + (size_t)bc*2*M1*M2*2;
    for (int e = t; e < 2*M1*M2*2; e += 1024) sD[e] = src[e];
    for (int e = t; e < M2*Hh; e += 1024) { sc[e] = g_cx[e]; ss[e] = g_sx[e]; }
    __syncthreads();

    // ---- phase 1: inv-y (identical arithmetic to previous k_invy) ----
    if (t < 640) {
        int kx = t % 20, yb = t / 20;                 // yb in [0,32)
        float scale = (kx == 0) ? (1.0f/256.0f) : (2.0f/256.0f);
        for (int jj = 0; jj < 8; jj++) {
            int y = yb + 32*jj;
            float ar = 0.f, ai = 0.f;
#pragma unroll 8
            for (int kyi = 0; kyi < 40; kyi++) {
                float dr = sD[(kyi*20 + kx)*2], di = sD[(kyi*20 + kx)*2 + 1];
                float c = __ldg(&g_cy[y*40 + kyi]), s = __ldg(&g_sy[y*40 + kyi]);
                ar += dr*c - di*s;                    // D * e^{+i th}
                ai += dr*s + di*c;
            }
            sg[y][2*kx]   = ar*scale;
            sg[y][2*kx+1] = ai*scale;
        }
    }
    __syncthreads();

    // ---- phase 2: inv-x + combine (identical arithmetic to previous k_invx) ----
    int x  = (t & 127) * 2;                           // x pair (x, x+1)
    int r0 = t >> 7;                                  // 0..7
    for (int it = 0; it < 32; it++) {
        int r = r0 + 8*it;
        unsigned long long val;
        PACKF2(val, sg[r][0]);                        // kx=0: Re only (C2R semantics)
#pragma unroll
        for (int k = 1; k < 20; k++) {
            unsigned long long gr2, gn2;
            float grv = sg[r][2*k], giv = sg[r][2*k+1];
            PACKF2(gr2, grv);
            PACKF2(gn2, -giv);
            unsigned long long c2 = *(const unsigned long long*)&sc[k*256 + x];
            unsigned long long s2 = *(const unsigned long long*)&ss[k*256 + x];
            FMA2(val, gr2, c2);                       // += gr*c
            FMA2(val, gn2, s2);                       // -= gi*s
        }
        size_t idx = ((size_t)bc*256 + r)*256 + x;
        float2 h2 = *(float2*)&hout[idx];
        float2 vf = *(float2*)&val;
        float h0v = h2.x + vf.x, h1v = h2.y + vf.y;
        if (do_gelu) {
            h0v = 0.5f*h0v*(1.0f + erff(h0v*0.70710678118654752440f));
            h1v = 0.5f*h1v*(1.0f + erff(h1v*0.70710678118654752440f));
        }
        *(float2*)&hout[idx] = make_float2(h0v, h1v);
    }
}

// ---------------- head: fc1 + gelu + fc2, d-paired f32x2 --------------------
__global__ __launch_bounds__(256) void k_head(const float* __restrict__ w1,
                                              const float* __restrict__ b1,
                                              const float* __restrict__ w2,
                                              const float* __restrict__ b2,
                                              float* __restrict__ out)
{
    __shared__ __align__(16) float sw1[64*128];
    __shared__ __align__(8)  float sb1[128];
    __shared__ float sw2[128];
    int t = threadIdx.x;
    for (int e = t; e < 64*128; e += 256) sw1[e] = w1[e];
    if (t < 128) { sb1[t] = b1[t]; sw2[t] = w2[t]; }
    __syncthreads();

    int pix = blockIdx.x * 256 + t;                   // over NPIX
    int x = pix & 255, y = (pix >> 8) & 255, b = pix >> 16;
    const float* hp = g_h0 + (size_t)b*64*HW + (size_t)y*256 + x;  // final h in g_h0

    float o = __ldg(&b2[0]);
    for (int half = 0; half < 2; half++) {
        unsigned long long acc[32];                   // (d, d+1) pairs, 64 d per half
#pragma unroll
        for (int dp = 0; dp < 32; dp++)
            acc[dp] = *(const unsigned long long*)&sb1[half*64 + 2*dp];
#pragma unroll 4
        for (int c = 0; c < 64; c++) {
            unsigned long long vv;
            PACKF2(vv, __ldg(&hp[(size_t)c*HW]));
            const ulonglong2* wp = (const ulonglong2*)&sw1[c*128 + half*64];
#pragma unroll
            for (int j = 0; j < 16; j++) {
                ulonglong2 w2p = wp[j];
                FMA2(acc[2*j],   vv, w2p.x);
                FMA2(acc[2*j+1], vv, w2p.y);
            }
        }
#pragma unroll
        for (int dp = 0; dp < 32; dp++) {
            float2 q = *(float2*)&acc[dp];
            float t0 = 0.5f*q.x*(1.0f + erff(q.x*0.70710678118654752440f));
            float t1 = 0.5f*q.y*(1.0f + erff(q.y*0.70710678118654752440f));
            o += t0 * sw2[half*64 + 2*dp];
            o += t1 * sw2[half*64 + 2*dp + 1];
        }
    }
    out[pix] = o;
}

// ---------------- launch -----------------------------------------------------
extern "C" void kernel_launch(void* const* d_in, const int* in_sizes, int n_in,
                              void* d_out, int out_size)
{
    const float* x    = (const float*)d_in[0];
    const float* fc0w = (const float*)d_in[1];
    const float* fc0b = (const float*)d_in[2];
    const float* w1   = (const float*)d_in[3];
    const float* w2   = (const float*)d_in[4];
    const float* chw  = (const float*)d_in[5];
    const float* chb  = (const float*)d_in[6];
    const float* cww  = (const float*)d_in[7];
    const float* cwb  = (const float*)d_in[8];
    const float* pww  = (const float*)d_in[9];
    const float* pwb  = (const float*)d_in[10];
    const float* f1w  = (const float*)d_in[11];
    const float* f1b  = (const float*)d_in[12];
    const float* f2w  = (const float*)d_in[13];
    const float* f2b  = (const float*)d_in[14];
    float* out = (float*)d_out;
    (void)in_sizes; (void)n_in; (void)out_size;

    k_prep_w<<<(Ll*Cc*Cc*9 + 255)/256, 256>>>(chw, cww, pww, chb, cwb, pwb);
    k_prep_wmix<<<512, 256>>>(w1, w2);
    k_prep_trig<<<40, 256>>>();
    k_fc0<<<NPIX/4/256, 256>>>(x, fc0w, fc0b);

    for (int l = 0; l < Ll; l++) {
        int sel = l & 1;                              // 0: h0->h1, 1: h1->h0
        k_conv<<<dim3(8, 32, 8), 256>>>(l, sel);
        k_fwd<<<BC, 1024>>>(sel);
        k_mix<<<800, 512>>>(l);
        k_inv<<<BC, 1024>>>(sel, (l < Ll-1) ? 1 : 0);
    }
    // after 4 layers (even count), final h is in g_h0
    k_head<<<NPIX/256, 256>>>(f1w, f1b, f2w, f2b, out);
}

// round 15
// speedup vs baseline: 1.0846x; 1.0846x over previous
#include <cuda_runtime.h>
#include <math.h>

#define Bn 8
#define Cc 64
#define Hh 256
#define Ww 256
#define Ll 4
#define M1 20
#define M2 20
#define BC (Bn*Cc)          // 512
#define HW (Hh*Ww)          // 65536
#define NPIX (Bn*HW)        // 524288
#define NTOT (BC*HW)        // 33554432

// packed f32x2 ops (sm_100+; only reachable via PTX — ptxas never auto-fuses)
#define FMA2(acc, a, b) \
    asm("fma.rn.f32x2 %0, %1, %2, %0;" : "+l"(acc) : "l"(a), "l"(b))
#define ADDF2(a, b) \
    asm("add.rn.f32x2 %0, %0, %1;" : "+l"(a) : "l"(b))
#define PACKF2(out, v) \
    asm("mov.b64 %0, {%1, %1};" : "=l"(out) : "r"(__float_as_uint(v)))

// cp.async (LDGSTS) helpers — no register staging, background copy
__device__ __forceinline__ void cp_async4(unsigned dst, const float* src, bool pred) {
    int sz = pred ? 4 : 0;                         // src-size 0 => zero-fill
    asm volatile("cp.async.ca.shared.global [%0], [%1], 4, %2;"
                 :: "r"(dst), "l"(src), "r"(sz));
}
__device__ __forceinline__ void cp_async16(unsigned dst, const float4* src) {
    asm volatile("cp.async.ca.shared.global [%0], [%1], 16;" :: "r"(dst), "l"(src));
}
#define CP_COMMIT() asm volatile("cp.async.commit_group;")
#define CP_WAIT0()  asm volatile("cp.async.wait_group 0;")

// ---------------- scratch (device globals; no allocations allowed) ----------
__device__ float g_h0[NTOT];                 // ping
__device__ float g_h1[NTOT];                 // pong
__device__ float g_xf[BC*Hh*M2*2];           // fwd-x result (bc,y,kx) complex
__device__ float g_F [BC*2*M1*M2*2];         // fwd-y result (bc,kyi,kx) complex
__device__ float g_D [BC*2*M1*M2*2];         // after channel mix
__device__ float g_gy[BC*Hh*M2*2];           // inv-y result (bc,y,kx) complex, pre-scaled
__device__ float g_wt[Ll*Cc*9*Cc];           // combined conv weights [l][ci][tap][co]
__device__ float g_bc2[Ll*Cc];               // combined conv bias
__device__ float g_wm[Ll*40*20*Cc*Cc*2];     // mode-contiguous mix weights [l][kyi][kx][i][o][2]
__device__ float g_cx[M2*Hh];                // cos(2pi k x/256), [k][x]
__device__ float g_sx[M2*Hh];                // sin(2pi k x/256), [k][x]
__device__ float g_cx2[10*Hh*2];             // paired cos: [kp][x][{2kp, 2kp+1}]
__device__ float g_sx2[10*Hh*2];             // paired sin
__device__ float g_cy[Hh*2*M1];              // [y][kyi], ky = kyi<20?kyi:216+kyi
__device__ float g_sy[Hh*2*M1];

// ---------------- prep: fold convh+convw+pw into one 3x3 conv ---------------
__global__ void k_prep_w(const float* __restrict__ ch, const float* __restrict__ cw,
                         const float* __restrict__ pw, const float* __restrict__ bh,
                         const float* __restrict__ bw, const float* __restrict__ bp)
{
    int idx = blockIdx.x*blockDim.x + threadIdx.x;
    int total = Ll*Cc*Cc*9;
    if (idx < total) {
        // destination layout: [l][ci][tap][co]  (co fastest -> co-pairs are contiguous)
        int co  = idx & 63;
        int tap = (idx >> 6) % 9;
        int ci  = (idx / (64*9)) & 63;
        int l   = idx / (64*9*64);
        int src = ((l*64 + co)*64 + ci)*9 + tap;       // source: (L,O,I,3,3)
        float v = ch[src] + cw[src];
        if (tap == 4) v += pw[(l*64 + co)*64 + ci];    // 1x1 folded into center
        g_wt[idx] = v;
    }
    if (idx < Ll*Cc) g_bc2[idx] = bh[idx] + bw[idx] + bp[idx];
}

// repack spectral weights, both directions coalesced via smem staging.
// block = (arr, l, i); loops 8 o-chunks; src rows contiguous, dst 64B chunks.
__global__ __launch_bounds__(256) void k_prep_wmix(const float* __restrict__ w1,
                                                   const float* __restrict__ w2)
{
    int bid = blockIdx.x;                              // 512 blocks
    int i   = bid & 63;
    int l   = (bid >> 6) & 3;
    int arr = bid >> 8;
    const float* w = arr ? w2 : w1;
    __shared__ float sm[8*800];
    int t = threadIdx.x;

    for (int oc = 0; oc < 8; oc++) {
        __syncthreads();
        const float* src = w + ((size_t)(l*64 + i)*64 + oc*8)*800;  // 8 o-rows x 800 floats
        for (int e = t; e < 8*800; e += 256) sm[e] = src[e];
        __syncthreads();
        for (int e = t; e < 400*16; e += 256) {
            int m = e >> 4, f = e & 15;                // m = kk*20+kx
            int o = oc*8 + (f >> 1), ri = f & 1;
            int kk = m / 20, kx = m % 20;
            int kyi = arr ? (20 + kk) : kk;
            g_wm[((((size_t)(l*40 + kyi)*20 + kx)*64 + i)*64 + o)*2 + ri] =
                sm[(o - oc*8)*800 + m*2 + ri];
        }
    }
}

__global__ void k_prep_trig()
{
    int idx = blockIdx.x*blockDim.x + threadIdx.x;
    if (idx < M2*Hh) {                                  // [k][x]
        int k = idx >> 8, x = idx & 255;
        int m = (k*x) & 255;                            // exact angle reduction
        double t = (double)m * (6.283185307179586476925287 / 256.0);
        double s, c; sincos(t, &s, &c);
        g_cx[idx] = (float)c; g_sx[idx] = (float)s;
    }
    if (idx < 10*Hh) {                                  // paired [kp][x] (k=2kp, 2kp+1)
        int kp = idx >> 8, x = idx & 255;
        int m0 = ((2*kp)*x) & 255;
        int m1 = ((2*kp+1)*x) & 255;
        double t0 = (double)m0 * (6.283185307179586476925287 / 256.0);
        double t1 = (double)m1 * (6.283185307179586476925287 / 256.0);
        double s0, c0, s1, c1; sincos(t0, &s0, &c0); sincos(t1, &s1, &c1);
        g_cx2[idx*2]   = (float)c0; g_cx2[idx*2+1] = (float)c1;
        g_sx2[idx*2]   = (float)s0; g_sx2[idx*2+1] = (float)s1;
    }
    if (idx < Hh*2*M1) {                                // [y][kyi]
        int y = idx / 40, kyi = idx % 40;
        int ky = (kyi < 20) ? kyi : (216 + kyi);        // 236..255
        int m = (ky*y) & 255;
        double t = (double)m * (6.283185307179586476925287 / 256.0);
        double s, c; sincos(t, &s, &c);
        g_cy[idx] = (float)c; g_sy[idx] = (float)s;
    }
}

// ---------------- fc0 lift: thread = 4 px x all 64 c ------------------------
__global__ __launch_bounds__(256) void k_fc0(const float* __restrict__ xin,
                                             const float* __restrict__ w,
                                             const float* __restrict__ b)
{
    int i4 = blockIdx.x*256 + threadIdx.x;              // over NPIX/4 = 131072
    if (i4 >= NPIX/4) return;
    int x4 = (i4 & 63) * 4;
    int y  = (i4 >> 6) & 255;
    int bb = i4 >> 14;
    const float* xp = xin + ((size_t)(bb*Hh + y)*Ww + x4)*3;
    float4 p0 = *(const float4*)(xp);                   // 12 consecutive floats
    float4 p1 = *(const float4*)(xp + 4);
    float4 p2 = *(const float4*)(xp + 8);
    float v0x = p0.x, v0y = p0.y, v0z = p0.z;           // px0
    float v1x = p0.w, v1y = p1.x, v1z = p1.y;           // px1
    float v2x = p1.z, v2y = p1.w, v2z = p2.x;           // px2
    float v3x = p2.y, v3y = p2.z, v3z = p2.w;           // px3
    float* dst = g_h0 + (size_t)bb*Cc*HW + (size_t)y*256 + x4;
#pragma unroll 4
    for (int c = 0; c < 64; c++) {
        float w0 = __ldg(&w[c]), w1 = __ldg(&w[64+c]), w2 = __ldg(&w[128+c]);
        float bs = __ldg(&b[c]);
        float4 r;
        r.x = bs + v0x*w0 + v0y*w1 + v0z*w2;
        r.y = bs + v1x*w0 + v1y*w1 + v1z*w2;
        r.z = bs + v2x*w0 + v2y*w1 + v2z*w2;
        r.w = bs + v3x*w0 + v3y*w1 + v3z*w2;
        *(float4*)&dst[(size_t)c*HW] = r;
    }
}

// ---------------- combined 3x3 conv (NCHW), f32x2 + cp.async pipeline -------
__global__ __launch_bounds__(256, 2) void k_conv(int l, int sel)
{
    const float* hin = sel ? g_h1 : g_h0;
    float*      hout = sel ? g_h0 : g_h1;

    __shared__ float s_in[2][8][10][36];              // 2 x 11.25KB
    __shared__ __align__(16) float s_w[2][8*9*64];    // 2 x 18KB

    int t  = threadIdx.x;
    int cog = t & 7;                                  // co group: 8 co each
    int p   = t >> 3;                                 // 0..31 pixel group
    int px8 = (p & 3) * 8;                            // x offset within tile
    int py  = p >> 2;                                 // 0..7
    int x0 = blockIdx.x * 32;
    int y0 = blockIdx.y * 8;
    int b  = blockIdx.z;
    const float* hb = hin + (size_t)b*Cc*HW;

    auto issue = [&](int cc, int buf) {
        unsigned sin_b = (unsigned)__cvta_generic_to_shared(&s_in[buf][0][0][0]);
        unsigned sw_b  = (unsigned)__cvta_generic_to_shared(&s_w[buf][0]);
        for (int e = t; e < 8*10*34; e += 256) {
            int ci = e / 340;
            int r  = e % 340;
            int dy = r / 34, dx = r % 34;
            int gy = y0 + dy - 1, gx = x0 + dx - 1;
            bool ok = (gy >= 0 && gy < 256 && gx >= 0 && gx < 256);
            const float* src = ok ? &hb[(size_t)(cc*8 + ci)*HW + gy*256 + gx] : hb;
            cp_async4(sin_b + (unsigned)(((ci*10 + dy)*36 + dx)*4), src, ok);
        }
        const float4* wsrc = (const float4*)&g_wt[((l*64 + cc*8)*9)*64];
        for (int e = t; e < 8*9*16; e += 256)
            cp_async16(sw_b + (unsigned)(e*16), wsrc + e);
        CP_COMMIT();
    };

    unsigned long long accp[4][8];
#pragma unroll
    for (int i = 0; i < 4; i++)
#pragma unroll
        for (int q = 0; q < 8; q++) accp[i][q] = 0ULL;   // (0.f,0.f)

    issue(0, 0);
    for (int cc = 0; cc < 8; cc++) {
        int buf = cc & 1;
        CP_WAIT0();
        __syncthreads();
        if (cc < 7) issue(cc + 1, buf ^ 1);

#pragma unroll
        for (int ci = 0; ci < 8; ci++) {
#pragma unroll
            for (int fy = 0; fy < 3; fy++) {
                const float* rp = &s_in[buf][ci][py+fy][px8];
                float4 a4 = *(const float4*)rp;
                float4 b4 = *(const float4*)(rp + 4);
                float2 c2 = *(const float2*)(rp + 8);
                unsigned long long xs[10];
                PACKF2(xs[0], a4.x); PACKF2(xs[1], a4.y);
                PACKF2(xs[2], a4.z); PACKF2(xs[3], a4.w);
                PACKF2(xs[4], b4.x); PACKF2(xs[5], b4.y);
                PACKF2(xs[6], b4.z); PACKF2(xs[7], b4.w);
                PACKF2(xs[8], c2.x); PACKF2(xs[9], c2.y);
#pragma unroll
                for (int fx = 0; fx < 3; fx++) {
                    const ulonglong2* wp =
                        (const ulonglong2*)&s_w[buf][(ci*9 + fy*3 + fx)*64 + cog*8];
                    ulonglong2 w0 = wp[0];
                    ulonglong2 w1 = wp[1];
#pragma unroll
                    for (int q = 0; q < 8; q++) {
                        FMA2(accp[0][q], w0.x, xs[fx+q]);
                        FMA2(accp[1][q], w0.y, xs[fx+q]);
                        FMA2(accp[2][q], w1.x, xs[fx+q]);
                        FMA2(accp[3][q], w1.y, xs[fx+q]);
                    }
                }
            }
        }
    }

    float* ob = hout + (size_t)b*Cc*HW + (size_t)(y0+py)*256 + (x0+px8);
#pragma unroll
    for (int pr = 0; pr < 4; pr++) {
        int co0 = cog*8 + 2*pr;
        float b0 = __ldg(&g_bc2[l*64 + co0]);
        float b1 = __ldg(&g_bc2[l*64 + co0 + 1]);
        float2 q0 = *(float2*)&accp[pr][0];
        float2 q1 = *(float2*)&accp[pr][1];
        float2 q2 = *(float2*)&accp[pr][2];
        float2 q3 = *(float2*)&accp[pr][3];
        float2 q4 = *(float2*)&accp[pr][4];
        float2 q5 = *(float2*)&accp[pr][5];
        float2 q6 = *(float2*)&accp[pr][6];
        float2 q7 = *(float2*)&accp[pr][7];
        float* r0 = &ob[(size_t)co0*HW];
        float* r1 = &ob[(size_t)(co0+1)*HW];
        *(float4*)(r0    ) = make_float4(q0.x+b0, q1.x+b0, q2.x+b0, q3.x+b0);
        *(float4*)(r0 + 4) = make_float4(q4.x+b0, q5.x+b0, q6.x+b0, q7.x+b0);
        *(float4*)(r1    ) = make_float4(q0.y+b1, q1.y+b1, q2.y+b1, q3.y+b1);
        *(float4*)(r1 + 4) = make_float4(q4.y+b1, q5.y+b1, q6.y+b1, q7.y+b1);
    }
}

// ---------------- forward partial DFT along x: 20 modes, k-paired f32x2 -----
__global__ __launch_bounds__(512) void k_fwdx(int sel)
{
    const float* hin = sel ? g_h1 : g_h0;
    __shared__ __align__(8) float sc2[10*Hh*2];
    __shared__ __align__(8) float ss2[10*Hh*2];
    int t = threadIdx.x;
    for (int e = t; e < 10*Hh*2; e += 512) { sc2[e] = g_cx2[e]; ss2[e] = g_sx2[e]; }
    __syncthreads();

    int warp = t >> 5, lane = t & 31;
    int row0 = blockIdx.x * 64 + warp * 4;            // 16 warps x 4 rows
    for (int rr = 0; rr < 4; rr++) {
        int row = row0 + rr;
        const float* rp = hin + (size_t)row * 256;
        unsigned long long vs[8];
#pragma unroll
        for (int j = 0; j < 8; j++) { float v = rp[lane + 32*j]; PACKF2(vs[j], v); }

        float* outp = g_xf + (size_t)row * (M2*2);
        for (int kp = 0; kp < 10; kp++) {
            unsigned long long ar = 0ULL, ai = 0ULL;
#pragma unroll
            for (int j = 0; j < 8; j++) {
                int x = lane + 32*j;
                unsigned long long c2 = *(const unsigned long long*)&sc2[(kp*256 + x)*2];
                unsigned long long s2 = *(const unsigned long long*)&ss2[(kp*256 + x)*2];
                FMA2(ar, vs[j], c2);
                FMA2(ai, vs[j], s2);
            }
#pragma unroll
            for (int o = 16; o > 0; o >>= 1) {
                unsigned long long t1 = __shfl_xor_sync(0xffffffffu, ar, o);
                unsigned long long t2 = __shfl_xor_sync(0xffffffffu, ai, o);
                ADDF2(ar, t1);
                ADDF2(ai, t2);
            }
            if (lane == 0) {
                float2 arf = *(float2*)&ar;
                float2 aif = *(float2*)&ai;
                outp[4*kp+0] =  arf.x*0.0625f;
                outp[4*kp+1] = -(aif.x*0.0625f);
                outp[4*kp+2] =  arf.y*0.0625f;
                outp[4*kp+3] = -(aif.y*0.0625f);
            }
        }
    }
}

// ---------------- forward partial DFT along y: 40 modes (0..19, 236..255) ---
__global__ __launch_bounds__(800) void k_fwdy()
{
    __shared__ float sX[Hh*M2*2];                     // 40KB slab for this image
    int bc = blockIdx.x;
    int t  = threadIdx.x;
    const float* src = g_xf + (size_t)bc * (Hh*M2*2);
    for (int e = t; e < Hh*M2*2; e += 800) sX[e] = src[e];
    __syncthreads();

    int kx = t % 20, kyi = t / 20;                    // kyi in [0,40)
    float ar = 0.f, ai = 0.f;
#pragma unroll 4
    for (int y = 0; y < 256; y++) {
        float xr = sX[(y*20 + kx)*2], xi = sX[(y*20 + kx)*2 + 1];
        float c = __ldg(&g_cy[y*40 + kyi]), s = __ldg(&g_sy[y*40 + kyi]);
        ar += xr*c + xi*s;                            // X * e^{-i th}
        ai += xi*c - xr*s;
    }
    size_t o = ((size_t)(bc*40 + kyi)*20 + kx)*2;
    g_F[o]   = ar*0.0625f;
    g_F[o+1] = ai*0.0625f;
}

// ---------------- per-mode 64x64 complex channel mix ------------------------
__global__ __launch_bounds__(512) void k_mix(int l)
{
    __shared__ __align__(16) float sW[Cc*Cc*2];       // [i][o] complex, 32KB
    __shared__ float sF[Bn*Cc*2];                     // [b][i] complex, 4KB
    int m   = blockIdx.x;                             // 0..799
    int kyi = m / 20, kx = m % 20;
    int t = threadIdx.x;

    {
        const float4* src4 = (const float4*)&g_wm[(size_t)(l*800 + m) * (Cc*Cc*2)];
        float4* dst4 = (float4*)sW;
        for (int e = t; e < Cc*Cc*2/4; e += 512) dst4[e] = src4[e];
    }
    {
        int e = t;                                    // e = b*64+i  (512 threads)
        size_t s = (((size_t)e*40 + kyi)*20 + kx)*2;
        sF[e*2]   = g_F[s];
        sF[e*2+1] = g_F[s+1];
    }
    __syncthreads();

    int o = t & 63, b = t >> 6;
    float ar = 0.f, ai = 0.f;
#pragma unroll 4
    for (int i = 0; i < 64; i++) {
        float fr = sF[(b*64 + i)*2], fi = sF[(b*64 + i)*2 + 1];
        float wr = sW[(i*64 + o)*2], wi = sW[(i*64 + o)*2 + 1];
        ar += fr*wr - fi*wi;
        ai += fr*wi + fi*wr;
    }
    size_t d = (((size_t)(b*64 + o)*40 + kyi)*20 + kx)*2;
    g_D[d] = ar; g_D[d+1] = ai;
}

// ---------------- inverse DFT along y (pre-scales for inv-x) ----------------
__global__ __launch_bounds__(640) void k_invy()
{
    __shared__ float sD[2*M1*M2*2];                   // 1600 floats
    int bc = blockIdx.x;
    int t  = threadIdx.x;
    const float* src = g_D + (size_t)bc*2*M1*M2*2;
    for (int e = t; e < 2*M1*M2*2; e += 640) sD[e] = src[e];
    __syncthreads();

    int kx = t % 20, yb = t / 20;                     // yb in [0,32)
    float scale = (kx == 0) ? (1.0f/256.0f) : (2.0f/256.0f);
    for (int jj = 0; jj < 8; jj++) {
        int y = yb + 32*jj;
        float ar = 0.f, ai = 0.f;
#pragma unroll 8
        for (int kyi = 0; kyi < 40; kyi++) {
            float dr = sD[(kyi*20 + kx)*2], di = sD[(kyi*20 + kx)*2 + 1];
            float c = __ldg(&g_cy[y*40 + kyi]), s = __ldg(&g_sy[y*40 + kyi]);
            ar += dr*c - di*s;                        // D * e^{+i th}
            ai += dr*s + di*c;
        }
        size_t o = ((size_t)(bc*256 + y)*20 + kx)*2;
        g_gy[o] = ar*scale; g_gy[o+1] = ai*scale;
    }
}

// ---------------- inverse DFT along x + add conv + GeLU, x-paired f32x2 -----
__global__ __launch_bounds__(512) void k_invx(int sel, int do_gelu)
{
    float* hout = sel ? g_h0 : g_h1;                  // conv output buffer
    __shared__ __align__(8) float sc[M2*Hh];
    __shared__ __align__(8) float ss[M2*Hh];
    __shared__ float sg[64][40];
    int t = threadIdx.x;
    for (int e = t; e < M2*Hh; e += 512) { sc[e] = g_cx[e]; ss[e] = g_sx[e]; }

    int bc = blockIdx.x;
    int y0 = blockIdx.y * 64;
    for (int e = t; e < 64*40; e += 512) {
        sg[e/40][e%40] = g_gy[((size_t)(bc*256 + y0 + e/40))*40 + e%40];
    }
    __syncthreads();

    int x  = (t & 127) * 2;                           // x pair (x, x+1)
    int r0 = t >> 7;                                  // 0..3
    for (int it = 0; it < 16; it++) {
        int r = r0 + 4*it;
        unsigned long long val;
        PACKF2(val, sg[r][0]);                        // kx=0: Re only (C2R semantics)
#pragma unroll
        for (int k = 1; k < 20; k++) {
            unsigned long long gr2, gn2;
            float grv = sg[r][2*k], giv = sg[r][2*k+1];
            PACKF2(gr2, grv);
            PACKF2(gn2, -giv);
            unsigned long long c2 = *(const unsigned long long*)&sc[k*256 + x];
            unsigned long long s2 = *(const unsigned long long*)&ss[k*256 + x];
            FMA2(val, gr2, c2);                       // += gr*c
            FMA2(val, gn2, s2);                       // -= gi*s
        }
        size_t idx = ((size_t)(bc*256 + y0 + r))*256 + x;
        float2 h2 = *(float2*)&hout[idx];
        float2 vf = *(float2*)&val;
        float h0v = h2.x + vf.x, h1v = h2.y + vf.y;
        if (do_gelu) {
            h0v = 0.5f*h0v*(1.0f + erff(h0v*0.70710678118654752440f));
            h1v = 0.5f*h1v*(1.0f + erff(h1v*0.70710678118654752440f));
        }
        *(float2*)&hout[idx] = make_float2(h0v, h1v);
    }
}

// ---------------- head: fc1 + gelu + fc2, d-paired f32x2 --------------------
__global__ __launch_bounds__(256) void k_head(const float* __restrict__ w1,
                                              const float* __restrict__ b1,
                                              const float* __restrict__ w2,
                                              const float* __restrict__ b2,
                                              float* __restrict__ out)
{
    __shared__ __align__(16) float sw1[64*128];
    __shared__ __align__(8)  float sb1[128];
    __shared__ float sw2[128];
    int t = threadIdx.x;
    for (int e = t; e < 64*128; e += 256) sw1[e] = w1[e];
    if (t < 128) { sb1[t] = b1[t]; sw2[t] = w2[t]; }
    __syncthreads();

    int pix = blockIdx.x * 256 + t;                   // over NPIX
    int x = pix & 255, y = (pix >> 8) & 255, b = pix >> 16;
    const float* hp = g_h0 + (size_t)b*64*HW + (size_t)y*256 + x;  // final h in g_h0

    float o = __ldg(&b2[0]);
    for (int half = 0; half < 2; half++) {
        unsigned long long acc[32];                   // (d, d+1) pairs, 64 d per half
#pragma unroll
        for (int dp = 0; dp < 32; dp++)
            acc[dp] = *(const unsigned long long*)&sb1[half*64 + 2*dp];
#pragma unroll 4
        for (int c = 0; c < 64; c++) {
            unsigned long long vv;
            PACKF2(vv, __ldg(&hp[(size_t)c*HW]));
            const ulonglong2* wp = (const ulonglong2*)&sw1[c*128 + half*64];
#pragma unroll
            for (int j = 0; j < 16; j++) {
                ulonglong2 w2p = wp[j];
                FMA2(acc[2*j],   vv, w2p.x);
                FMA2(acc[2*j+1], vv, w2p.y);
            }
        }
#pragma unroll
        for (int dp = 0; dp < 32; dp++) {
            float2 q = *(float2*)&acc[dp];
            float t0 = 0.5f*q.x*(1.0f + erff(q.x*0.70710678118654752440f));
            float t1 = 0.5f*q.y*(1.0f + erff(q.y*0.70710678118654752440f));
            o += t0 * sw2[half*64 + 2*dp];
            o += t1 * sw2[half*64 + 2*dp + 1];
        }
    }
    out[pix] = o;
}

// ---------------- launch -----------------------------------------------------
extern "C" void kernel_launch(void* const* d_in, const int* in_sizes, int n_in,
                              void* d_out, int out_size)
{
    const float* x    = (const float*)d_in[0];
    const float* fc0w = (const float*)d_in[1];
    const float* fc0b = (const float*)d_in[2];
    const float* w1   = (const float*)d_in[3];
    const float* w2   = (const float*)d_in[4];
    const float* chw  = (const float*)d_in[5];
    const float* chb  = (const float*)d_in[6];
    const float* cww  = (const float*)d_in[7];
    const float* cwb  = (const float*)d_in[8];
    const float* pww  = (const float*)d_in[9];
    const float* pwb  = (const float*)d_in[10];
    const float* f1w  = (const float*)d_in[11];
    const float* f1b  = (const float*)d_in[12];
    const float* f2w  = (const float*)d_in[13];
    const float* f2b  = (const float*)d_in[14];
    float* out = (float*)d_out;
    (void)in_sizes; (void)n_in; (void)out_size;

    k_prep_w<<<(Ll*Cc*Cc*9 + 255)/256, 256>>>(chw, cww, pww, chb, cwb, pwb);
    k_prep_wmix<<<512, 256>>>(w1, w2);
    k_prep_trig<<<40, 256>>>();
    k_fc0<<<NPIX/4/256, 256>>>(x, fc0w, fc0b);

    for (int l = 0; l < Ll; l++) {
        int sel = l & 1;                              // 0: h0->h1, 1: h1->h0
        k_conv<<<dim3(8, 32, 8), 256>>>(l, sel);
        k_fwdx<<<BC*Hh/64, 512>>>(sel);
        k_fwdy<<<BC, 800>>>();
        k_mix<<<800, 512>>>(l);
        k_invy<<<BC, 640>>>();
        k_invx<<<dim3(BC, 4), 512>>>(sel, (l < Ll-1) ? 1 : 0);
    }
    // after 4 layers (even count), final h is in g_h0
    k_head<<<NPIX/256, 256>>>(f1w, f1b, f2w, f2b, out);
}

// round 16
// speedup vs baseline: 1.0973x; 1.0117x over previous
#include <cuda_runtime.h>
#include <math.h>

#define Bn 8
#define Cc 64
#define Hh 256
#define Ww 256
#define Ll 4
#define M1 20
#define M2 20
#define BC (Bn*Cc)          // 512
#define HW (Hh*Ww)          // 65536
#define NPIX (Bn*HW)        // 524288
#define NTOT (BC*HW)        // 33554432

// packed f32x2 ops (sm_100+; only reachable via PTX — ptxas never auto-fuses)
#define FMA2(acc, a, b) \
    asm("fma.rn.f32x2 %0, %1, %2, %0;" : "+l"(acc) : "l"(a), "l"(b))
#define ADDF2(a, b) \
    asm("add.rn.f32x2 %0, %0, %1;" : "+l"(a) : "l"(b))
#define PACKF2(out, v) \
    asm("mov.b64 %0, {%1, %1};" : "=l"(out) : "r"(__float_as_uint(v)))

// cp.async (LDGSTS) helpers — no register staging, background copy
__device__ __forceinline__ void cp_async4(unsigned dst, const float* src, bool pred) {
    int sz = pred ? 4 : 0;                         // src-size 0 => zero-fill
    asm volatile("cp.async.ca.shared.global [%0], [%1], 4, %2;"
                 :: "r"(dst), "l"(src), "r"(sz));
}
__device__ __forceinline__ void cp_async16(unsigned dst, const float4* src) {
    asm volatile("cp.async.ca.shared.global [%0], [%1], 16;" :: "r"(dst), "l"(src));
}
#define CP_COMMIT() asm volatile("cp.async.commit_group;")
#define CP_WAIT0()  asm volatile("cp.async.wait_group 0;")

// ---------------- scratch (device globals; no allocations allowed) ----------
__device__ float g_h0[NTOT];                 // ping
__device__ float g_h1[NTOT];                 // pong
__device__ float g_xf[BC*Hh*M2*2];           // fwd-x result (bc,y,kx) complex
__device__ float g_F [BC*2*M1*M2*2];         // fwd-y result (bc,kyi,kx) complex
__device__ float g_D [BC*2*M1*M2*2];         // after channel mix
__device__ float g_gy[BC*Hh*M2*2];           // inv-y result (bc,y,kx) complex, pre-scaled
__device__ float g_wt[Ll*Cc*9*Cc];           // combined conv weights [l][ci][tap][co]
__device__ float g_bc2[Ll*Cc];               // combined conv bias
__device__ float g_wm[Ll*40*20*Cc*Cc*2];     // mode-contiguous mix weights [l][kyi][kx][i][o][2]
__device__ float g_cx[M2*Hh];                // cos(2pi k x/256), [k][x]
__device__ float g_sx[M2*Hh];                // sin(2pi k x/256), [k][x]
__device__ float g_cx2[10*Hh*2];             // paired cos: [kp][x][{2kp, 2kp+1}]
__device__ float g_sx2[10*Hh*2];             // paired sin
__device__ float g_cy[Hh*2*M1];              // [y][kyi], ky = kyi<20?kyi:216+kyi
__device__ float g_sy[Hh*2*M1];

// ---------------- prep: fold convh+convw+pw into one 3x3 conv ---------------
__global__ void k_prep_w(const float* __restrict__ ch, const float* __restrict__ cw,
                         const float* __restrict__ pw, const float* __restrict__ bh,
                         const float* __restrict__ bw, const float* __restrict__ bp)
{
    int idx = blockIdx.x*blockDim.x + threadIdx.x;
    int total = Ll*Cc*Cc*9;
    if (idx < total) {
        // destination layout: [l][ci][tap][co]  (co fastest -> co-pairs are contiguous)
        int co  = idx & 63;
        int tap = (idx >> 6) % 9;
        int ci  = (idx / (64*9)) & 63;
        int l   = idx / (64*9*64);
        int src = ((l*64 + co)*64 + ci)*9 + tap;       // source: (L,O,I,3,3)
        float v = ch[src] + cw[src];
        if (tap == 4) v += pw[(l*64 + co)*64 + ci];    // 1x1 folded into center
        g_wt[idx] = v;
    }
    if (idx < Ll*Cc) g_bc2[idx] = bh[idx] + bw[idx] + bp[idx];
}

// repack spectral weights, both directions coalesced via smem staging.
// block = (arr, l, i); loops 8 o-chunks; src rows contiguous, dst 64B chunks.
__global__ __launch_bounds__(256) void k_prep_wmix(const float* __restrict__ w1,
                                                   const float* __restrict__ w2)
{
    int bid = blockIdx.x;                              // 512 blocks
    int i   = bid & 63;
    int l   = (bid >> 6) & 3;
    int arr = bid >> 8;
    const float* w = arr ? w2 : w1;
    __shared__ float sm[8*800];
    int t = threadIdx.x;

    for (int oc = 0; oc < 8; oc++) {
        __syncthreads();
        const float* src = w + ((size_t)(l*64 + i)*64 + oc*8)*800;  // 8 o-rows x 800 floats
        for (int e = t; e < 8*800; e += 256) sm[e] = src[e];
        __syncthreads();
        for (int e = t; e < 400*16; e += 256) {
            int m = e >> 4, f = e & 15;                // m = kk*20+kx
            int o = oc*8 + (f >> 1), ri = f & 1;
            int kk = m / 20, kx = m % 20;
            int kyi = arr ? (20 + kk) : kk;
            g_wm[((((size_t)(l*40 + kyi)*20 + kx)*64 + i)*64 + o)*2 + ri] =
                sm[(o - oc*8)*800 + m*2 + ri];
        }
    }
}

__global__ void k_prep_trig()
{
    int idx = blockIdx.x*blockDim.x + threadIdx.x;
    if (idx < M2*Hh) {                                  // [k][x]
        int k = idx >> 8, x = idx & 255;
        int m = (k*x) & 255;                            // exact angle reduction
        double t = (double)m * (6.283185307179586476925287 / 256.0);
        double s, c; sincos(t, &s, &c);
        g_cx[idx] = (float)c; g_sx[idx] = (float)s;
    }
    if (idx < 10*Hh) {                                  // paired [kp][x] (k=2kp, 2kp+1)
        int kp = idx >> 8, x = idx & 255;
        int m0 = ((2*kp)*x) & 255;
        int m1 = ((2*kp+1)*x) & 255;
        double t0 = (double)m0 * (6.283185307179586476925287 / 256.0);
        double t1 = (double)m1 * (6.283185307179586476925287 / 256.0);
        double s0, c0, s1, c1; sincos(t0, &s0, &c0); sincos(t1, &s1, &c1);
        g_cx2[idx*2]   = (float)c0; g_cx2[idx*2+1] = (float)c1;
        g_sx2[idx*2]   = (float)s0; g_sx2[idx*2+1] = (float)s1;
    }
    if (idx < Hh*2*M1) {                                // [y][kyi]
        int y = idx / 40, kyi = idx % 40;
        int ky = (kyi < 20) ? kyi : (216 + kyi);        // 236..255
        int m = (ky*y) & 255;
        double t = (double)m * (6.283185307179586476925287 / 256.0);
        double s, c; sincos(t, &s, &c);
        g_cy[idx] = (float)c; g_sy[idx] = (float)s;
    }
}

// ---------------- fc0 lift: thread = 4 px x all 64 c ------------------------
__global__ __launch_bounds__(256) void k_fc0(const float* __restrict__ xin,
                                             const float* __restrict__ w,
                                             const float* __restrict__ b)
{
    int i4 = blockIdx.x*256 + threadIdx.x;              // over NPIX/4 = 131072
    if (i4 >= NPIX/4) return;
    int x4 = (i4 & 63) * 4;
    int y  = (i4 >> 6) & 255;
    int bb = i4 >> 14;
    const float* xp = xin + ((size_t)(bb*Hh + y)*Ww + x4)*3;
    float4 p0 = *(const float4*)(xp);                   // 12 consecutive floats
    float4 p1 = *(const float4*)(xp + 4);
    float4 p2 = *(const float4*)(xp + 8);
    float v0x = p0.x, v0y = p0.y, v0z = p0.z;           // px0
    float v1x = p0.w, v1y = p1.x, v1z = p1.y;           // px1
    float v2x = p1.z, v2y = p1.w, v2z = p2.x;           // px2
    float v3x = p2.y, v3y = p2.z, v3z = p2.w;           // px3
    float* dst = g_h0 + (size_t)bb*Cc*HW + (size_t)y*256 + x4;
#pragma unroll 4
    for (int c = 0; c < 64; c++) {
        float w0 = __ldg(&w[c]), w1 = __ldg(&w[64+c]), w2 = __ldg(&w[128+c]);
        float bs = __ldg(&b[c]);
        float4 r;
        r.x = bs + v0x*w0 + v0y*w1 + v0z*w2;
        r.y = bs + v1x*w0 + v1y*w1 + v1z*w2;
        r.z = bs + v2x*w0 + v2y*w1 + v2z*w2;
        r.w = bs + v3x*w0 + v3y*w1 + v3z*w2;
        *(float4*)&dst[(size_t)c*HW] = r;
    }
}

// ---------------- merged conv + fwdx (heterogeneous blocks) -----------------
// 3072 blocks, interleaved 2:1 — grp = bid/3; rem<2 -> conv block (2048 total),
// rem==2 -> fwdx block (1024 total). Both roles only READ h_in (conv writes
// h_out, fwdx writes g_xf) so they are freely concurrent; fwdx's latency-bound
// blocks fill the issue/memory slack of the FMA-bound conv blocks. Smem is a
// union within conv's existing 58.5KB footprint -> still 2 CTAs/SM.
// Arithmetic of both roles is bit-identical to the previous separate kernels.
__global__ __launch_bounds__(256, 2) void k_convfwd(int l, int sel)
{
    const float* hin = sel ? g_h1 : g_h0;
    float*      hout = sel ? g_h0 : g_h1;

    __shared__ __align__(16) union SMU {
        struct { float s_in[2][8][10][36]; float s_w[2][8*9*64]; } cv;  // 58.5KB
        struct { float sc2[10*Hh*2]; float ss2[10*Hh*2]; } fw;          // 40KB
    } smu;

    int bid = blockIdx.x;
    int grp = bid / 3, rem = bid - grp*3;
    int t = threadIdx.x;

    if (rem == 2) {
        // ================= fwdx role: 8 warps x 16 rows = 128 rows ==========
        float* sc2 = smu.fw.sc2;
        float* ss2 = smu.fw.ss2;
        for (int e = t; e < 10*Hh*2; e += 256) { sc2[e] = g_cx2[e]; ss2[e] = g_sx2[e]; }
        __syncthreads();

        int warp = t >> 5, lane = t & 31;
        int row0 = grp*128 + warp*16;
        for (int rr = 0; rr < 16; rr++) {
            int row = row0 + rr;
            const float* rp = hin + (size_t)row * 256;
            unsigned long long vs[8];
#pragma unroll
            for (int j = 0; j < 8; j++) { float v = rp[lane + 32*j]; PACKF2(vs[j], v); }

            float* outp = g_xf + (size_t)row * (M2*2);
            for (int kp = 0; kp < 10; kp++) {
                unsigned long long ar = 0ULL, ai = 0ULL;
#pragma unroll
                for (int j = 0; j < 8; j++) {
                    int x = lane + 32*j;
                    unsigned long long c2 = *(const unsigned long long*)&sc2[(kp*256 + x)*2];
                    unsigned long long s2 = *(const unsigned long long*)&ss2[(kp*256 + x)*2];
                    FMA2(ar, vs[j], c2);
                    FMA2(ai, vs[j], s2);
                }
#pragma unroll
                for (int o = 16; o > 0; o >>= 1) {
                    unsigned long long t1 = __shfl_xor_sync(0xffffffffu, ar, o);
                    unsigned long long t2 = __shfl_xor_sync(0xffffffffu, ai, o);
                    ADDF2(ar, t1);
                    ADDF2(ai, t2);
                }
                if (lane == 0) {
                    float2 arf = *(float2*)&ar;
                    float2 aif = *(float2*)&ai;
                    outp[4*kp+0] =  arf.x*0.0625f;
                    outp[4*kp+1] = -(aif.x*0.0625f);
                    outp[4*kp+2] =  arf.y*0.0625f;
                    outp[4*kp+3] = -(aif.y*0.0625f);
                }
            }
        }
        return;
    }

    // ================= conv role (identical arithmetic to k_conv) ===========
    int cidx = grp*2 + rem;                           // 0..2047
    int cog = t & 7;                                  // co group: 8 co each
    int p   = t >> 3;                                 // 0..31 pixel group
    int px8 = (p & 3) * 8;                            // x offset within tile
    int py  = p >> 2;                                 // 0..7
    int x0 = (cidx & 7) * 32;
    int y0 = ((cidx >> 3) & 31) * 8;
    int b  = cidx >> 8;
    const float* hb = hin + (size_t)b*Cc*HW;

    auto issue = [&](int cc, int buf) {
        unsigned sin_b = (unsigned)__cvta_generic_to_shared(&smu.cv.s_in[buf][0][0][0]);
        unsigned sw_b  = (unsigned)__cvta_generic_to_shared(&smu.cv.s_w[buf][0]);
        for (int e = t; e < 8*10*34; e += 256) {
            int ci = e / 340;
            int r  = e % 340;
            int dy = r / 34, dx = r % 34;
            int gy = y0 + dy - 1, gx = x0 + dx - 1;
            bool ok = (gy >= 0 && gy < 256 && gx >= 0 && gx < 256);
            const float* src = ok ? &hb[(size_t)(cc*8 + ci)*HW + gy*256 + gx] : hb;
            cp_async4(sin_b + (unsigned)(((ci*10 + dy)*36 + dx)*4), src, ok);
        }
        const float4* wsrc = (const float4*)&g_wt[((l*64 + cc*8)*9)*64];
        for (int e = t; e < 8*9*16; e += 256)
            cp_async16(sw_b + (unsigned)(e*16), wsrc + e);
        CP_COMMIT();
    };

    unsigned long long accp[4][8];
#pragma unroll
    for (int i = 0; i < 4; i++)
#pragma unroll
        for (int q = 0; q < 8; q++) accp[i][q] = 0ULL;   // (0.f,0.f)

    issue(0, 0);
    for (int cc = 0; cc < 8; cc++) {
        int buf = cc & 1;
        CP_WAIT0();
        __syncthreads();
        if (cc < 7) issue(cc + 1, buf ^ 1);

#pragma unroll
        for (int ci = 0; ci < 8; ci++) {
#pragma unroll
            for (int fy = 0; fy < 3; fy++) {
                const float* rp = &smu.cv.s_in[buf][ci][py+fy][px8];
                float4 a4 = *(const float4*)rp;
                float4 b4 = *(const float4*)(rp + 4);
                float2 c2 = *(const float2*)(rp + 8);
                unsigned long long xs[10];
                PACKF2(xs[0], a4.x); PACKF2(xs[1], a4.y);
                PACKF2(xs[2], a4.z); PACKF2(xs[3], a4.w);
                PACKF2(xs[4], b4.x); PACKF2(xs[5], b4.y);
                PACKF2(xs[6], b4.z); PACKF2(xs[7], b4.w);
                PACKF2(xs[8], c2.x); PACKF2(xs[9], c2.y);
#pragma unroll
                for (int fx = 0; fx < 3; fx++) {
                    const ulonglong2* wp =
                        (const ulonglong2*)&smu.cv.s_w[buf][(ci*9 + fy*3 + fx)*64 + cog*8];
                    ulonglong2 w0 = wp[0];
                    ulonglong2 w1 = wp[1];
#pragma unroll
                    for (int q = 0; q < 8; q++) {
                        FMA2(accp[0][q], w0.x, xs[fx+q]);
                        FMA2(accp[1][q], w0.y, xs[fx+q]);
                        FMA2(accp[2][q], w1.x, xs[fx+q]);
                        FMA2(accp[3][q], w1.y, xs[fx+q]);
                    }
                }
            }
        }
    }

    float* ob = hout + (size_t)b*Cc*HW + (size_t)(y0+py)*256 + (x0+px8);
#pragma unroll
    for (int pr = 0; pr < 4; pr++) {
        int co0 = cog*8 + 2*pr;
        float b0 = __ldg(&g_bc2[l*64 + co0]);
        float b1 = __ldg(&g_bc2[l*64 + co0 + 1]);
        float2 q0 = *(float2*)&accp[pr][0];
        float2 q1 = *(float2*)&accp[pr][1];
        float2 q2 = *(float2*)&accp[pr][2];
        float2 q3 = *(float2*)&accp[pr][3];
        float2 q4 = *(float2*)&accp[pr][4];
        float2 q5 = *(float2*)&accp[pr][5];
        float2 q6 = *(float2*)&accp[pr][6];
        float2 q7 = *(float2*)&accp[pr][7];
        float* r0 = &ob[(size_t)co0*HW];
        float* r1 = &ob[(size_t)(co0+1)*HW];
        *(float4*)(r0    ) = make_float4(q0.x+b0, q1.x+b0, q2.x+b0, q3.x+b0);
        *(float4*)(r0 + 4) = make_float4(q4.x+b0, q5.x+b0, q6.x+b0, q7.x+b0);
        *(float4*)(r1    ) = make_float4(q0.y+b1, q1.y+b1, q2.y+b1, q3.y+b1);
        *(float4*)(r1 + 4) = make_float4(q4.y+b1, q5.y+b1, q6.y+b1, q7.y+b1);
    }
}

// ---------------- forward partial DFT along y: 40 modes (0..19, 236..255) ---
__global__ __launch_bounds__(800) void k_fwdy()
{
    __shared__ float sX[Hh*M2*2];                     // 40KB slab for this image
    int bc = blockIdx.x;
    int t  = threadIdx.x;
    const float* src = g_xf + (size_t)bc * (Hh*M2*2);
    for (int e = t; e < Hh*M2*2; e += 800) sX[e] = src[e];
    __syncthreads();

    int kx = t % 20, kyi = t / 20;                    // kyi in [0,40)
    float ar = 0.f, ai = 0.f;
#pragma unroll 4
    for (int y = 0; y < 256; y++) {
        float xr = sX[(y*20 + kx)*2], xi = sX[(y*20 + kx)*2 + 1];
        float c = __ldg(&g_cy[y*40 + kyi]), s = __ldg(&g_sy[y*40 + kyi]);
        ar += xr*c + xi*s;                            // X * e^{-i th}
        ai += xi*c - xr*s;
    }
    size_t o = ((size_t)(bc*40 + kyi)*20 + kx)*2;
    g_F[o]   = ar*0.0625f;
    g_F[o+1] = ai*0.0625f;
}

// ---------------- per-mode 64x64 complex channel mix ------------------------
__global__ __launch_bounds__(512) void k_mix(int l)
{
    __shared__ __align__(16) float sW[Cc*Cc*2];       // [i][o] complex, 32KB
    __shared__ float sF[Bn*Cc*2];                     // [b][i] complex, 4KB
    int m   = blockIdx.x;                             // 0..799
    int kyi = m / 20, kx = m % 20;
    int t = threadIdx.x;

    {
        const float4* src4 = (const float4*)&g_wm[(size_t)(l*800 + m) * (Cc*Cc*2)];
        float4* dst4 = (float4*)sW;
        for (int e = t; e < Cc*Cc*2/4; e += 512) dst4[e] = src4[e];
    }
    {
        int e = t;                                    // e = b*64+i  (512 threads)
        size_t s = (((size_t)e*40 + kyi)*20 + kx)*2;
        sF[e*2]   = g_F[s];
        sF[e*2+1] = g_F[s+1];
    }
    __syncthreads();

    int o = t & 63, b = t >> 6;
    float ar = 0.f, ai = 0.f;
#pragma unroll 4
    for (int i = 0; i < 64; i++) {
        float fr = sF[(b*64 + i)*2], fi = sF[(b*64 + i)*2 + 1];
        float wr = sW[(i*64 + o)*2], wi = sW[(i*64 + o)*2 + 1];
        ar += fr*wr - fi*wi;
        ai += fr*wi + fi*wr;
    }
    size_t d = (((size_t)(b*64 + o)*40 + kyi)*20 + kx)*2;
    g_D[d] = ar; g_D[d+1] = ai;
}

// ---------------- inverse DFT along y (pre-scales for inv-x) ----------------
__global__ __launch_bounds__(640) void k_invy()
{
    __shared__ float sD[2*M1*M2*2];                   // 1600 floats
    int bc = blockIdx.x;
    int t  = threadIdx.x;
    const float* src = g_D + (size_t)bc*2*M1*M2*2;
    for (int e = t; e < 2*M1*M2*2; e += 640) sD[e] = src[e];
    __syncthreads();

    int kx = t % 20, yb = t / 20;                     // yb in [0,32)
    float scale = (kx == 0) ? (1.0f/256.0f) : (2.0f/256.0f);
    for (int jj = 0; jj < 8; jj++) {
        int y = yb + 32*jj;
        float ar = 0.f, ai = 0.f;
#pragma unroll 8
        for (int kyi = 0; kyi < 40; kyi++) {
            float dr = sD[(kyi*20 + kx)*2], di = sD[(kyi*20 + kx)*2 + 1];
            float c = __ldg(&g_cy[y*40 + kyi]), s = __ldg(&g_sy[y*40 + kyi]);
            ar += dr*c - di*s;                        // D * e^{+i th}
            ai += dr*s + di*c;
        }
        size_t o = ((size_t)(bc*256 + y)*20 + kx)*2;
        g_gy[o] = ar*scale; g_gy[o+1] = ai*scale;
    }
}

// ---------------- inverse DFT along x + add conv + GeLU, x-paired f32x2 -----
__global__ __launch_bounds__(512) void k_invx(int sel, int do_gelu)
{
    float* hout = sel ? g_h0 : g_h1;                  // conv output buffer
    __shared__ __align__(8) float sc[M2*Hh];
    __shared__ __align__(8) float ss[M2*Hh];
    __shared__ float sg[64][40];
    int t = threadIdx.x;
    for (int e = t; e < M2*Hh; e += 512) { sc[e] = g_cx[e]; ss[e] = g_sx[e]; }

    int bc = blockIdx.x;
    int y0 = blockIdx.y * 64;
    for (int e = t; e < 64*40; e += 512) {
        sg[e/40][e%40] = g_gy[((size_t)(bc*256 + y0 + e/40))*40 + e%40];
    }
    __syncthreads();

    int x  = (t & 127) * 2;                           // x pair (x, x+1)
    int r0 = t >> 7;                                  // 0..3
    for (int it = 0; it < 16; it++) {
        int r = r0 + 4*it;
        unsigned long long val;
        PACKF2(val, sg[r][0]);                        // kx=0: Re only (C2R semantics)
#pragma unroll
        for (int k = 1; k < 20; k++) {
            unsigned long long gr2, gn2;
            float grv = sg[r][2*k], giv = sg[r][2*k+1];
            PACKF2(gr2, grv);
            PACKF2(gn2, -giv);
            unsigned long long c2 = *(const unsigned long long*)&sc[k*256 + x];
            unsigned long long s2 = *(const unsigned long long*)&ss[k*256 + x];
            FMA2(val, gr2, c2);                       // += gr*c
            FMA2(val, gn2, s2);                       // -= gi*s
        }
        size_t idx = ((size_t)(bc*256 + y0 + r))*256 + x;
        float2 h2 = *(float2*)&hout[idx];
        float2 vf = *(float2*)&val;
        float h0v = h2.x + vf.x, h1v = h2.y + vf.y;
        if (do_gelu) {
            h0v = 0.5f*h0v*(1.0f + erff(h0v*0.70710678118654752440f));
            h1v = 0.5f*h1v*(1.0f + erff(h1v*0.70710678118654752440f));
        }
        *(float2*)&hout[idx] = make_float2(h0v, h1v);
    }
}

// ---------------- head: fc1 + gelu + fc2, d-paired f32x2 --------------------
__global__ __launch_bounds__(256) void k_head(const float* __restrict__ w1,
                                              const float* __restrict__ b1,
                                              const float* __restrict__ w2,
                                              const float* __restrict__ b2,
                                              float* __restrict__ out)
{
    __shared__ __align__(16) float sw1[64*128];
    __shared__ __align__(8)  float sb1[128];
    __shared__ float sw2[128];
    int t = threadIdx.x;
    for (int e = t; e < 64*128; e += 256) sw1[e] = w1[e];
    if (t < 128) { sb1[t] = b1[t]; sw2[t] = w2[t]; }
    __syncthreads();

    int pix = blockIdx.x * 256 + t;                   // over NPIX
    int x = pix & 255, y = (pix >> 8) & 255, b = pix >> 16;
    const float* hp = g_h0 + (size_t)b*64*HW + (size_t)y*256 + x;  // final h in g_h0

    float o = __ldg(&b2[0]);
    for (int half = 0; half < 2; half++) {
        unsigned long long acc[32];                   // (d, d+1) pairs, 64 d per half
#pragma unroll
        for (int dp = 0; dp < 32; dp++)
            acc[dp] = *(const unsigned long long*)&sb1[half*64 + 2*dp];
#pragma unroll 4
        for (int c = 0; c < 64; c++) {
            unsigned long long vv;
            PACKF2(vv, __ldg(&hp[(size_t)c*HW]));
            const ulonglong2* wp = (const ulonglong2*)&sw1[c*128 + half*64];
#pragma unroll
            for (int j = 0; j < 16; j++) {
                ulonglong2 w2p = wp[j];
                FMA2(acc[2*j],   vv, w2p.x);
                FMA2(acc[2*j+1], vv, w2p.y);
            }
        }
#pragma unroll
        for (int dp = 0; dp < 32; dp++) {
            float2 q = *(float2*)&acc[dp];
            float t0 = 0.5f*q.x*(1.0f + erff(q.x*0.70710678118654752440f));
            float t1 = 0.5f*q.y*(1.0f + erff(q.y*0.70710678118654752440f));
            o += t0 * sw2[half*64 + 2*dp];
            o += t1 * sw2[half*64 + 2*dp + 1];
        }
    }
    out[pix] = o;
}

// ---------------- launch -----------------------------------------------------
extern "C" void kernel_launch(void* const* d_in, const int* in_sizes, int n_in,
                              void* d_out, int out_size)
{
    const float* x    = (const float*)d_in[0];
    const float* fc0w = (const float*)d_in[1];
    const float* fc0b = (const float*)d_in[2];
    const float* w1   = (const float*)d_in[3];
    const float* w2   = (const float*)d_in[4];
    const float* chw  = (const float*)d_in[5];
    const float* chb  = (const float*)d_in[6];
    const float* cww  = (const float*)d_in[7];
    const float* cwb  = (const float*)d_in[8];
    const float* pww  = (const float*)d_in[9];
    const float* pwb  = (const float*)d_in[10];
    const float* f1w  = (const float*)d_in[11];
    const float* f1b  = (const float*)d_in[12];
    const float* f2w  = (const float*)d_in[13];
    const float* f2b  = (const float*)d_in[14];
    float* out = (float*)d_out;
    (void)in_sizes; (void)n_in; (void)out_size;

    k_prep_w<<<(Ll*Cc*Cc*9 + 255)/256, 256>>>(chw, cww, pww, chb, cwb, pwb);
    k_prep_wmix<<<512, 256>>>(w1, w2);
    k_prep_trig<<<40, 256>>>();
    k_fc0<<<NPIX/4/256, 256>>>(x, fc0w, fc0b);

    for (int l = 0; l < Ll; l++) {
        int sel = l & 1;                              // 0: h0->h1, 1: h1->h0
        k_convfwd<<<3072, 256>>>(l, sel);             // conv ∥ fwdx (independent)
        k_fwdy<<<BC, 800>>>();
        k_mix<<<800, 512>>>(l);
        k_invy<<<BC, 640>>>();
        k_invx<<<dim3(BC, 4), 512>>>(sel, (l < Ll-1) ? 1 : 0);
    }
    // after 4 layers (even count), final h is in g_h0
    k_head<<<NPIX/256, 256>>>(f1w, f1b, f2w, f2b, out);
}